// round 14
// baseline (speedup 1.0000x reference)
#include <cuda_runtime.h>
#include <cuda_bf16.h>
#include <math.h>
#include <stdint.h>

// ---------------- problem constants ----------------
#define BATCH   8192
#define TSTEPS  99
#define DIN     32
#define DH      100
#define RW      16
#define RU      25
#define NCLS    6
#define MROWS   64
#define NBLK    (BATCH / MROWS)      // 128
#define NTHR    448                  // 14 warps: 2(m) x 7(n)

// A: 64 x 296 bf16. cols: 0-111 Hhi, 112-223 Hlo, 224-255 xhi, 256-287 xlo
#define A_LD    296
#define A_BYTES (64 * A_LD * 2)      // 37888
// B: 288 x 136 bf16. rows: 0-111 Uhi, 112-223 Ulo, 224-255 Whi, 256-287 Wlo
#define B_LD    136
#define B_BYTES (288 * B_LD * 2)     // 78336

#define SM_A    0                    // double buffered: A[0], A[1]
#define SM_B    (SM_A + 2 * A_BYTES)
#define SM_BB   (SM_B + B_BYTES)
#define SM_SCR  (SM_BB + 1024)
#define SM_TOT  (SM_SCR + 1536)      // 156672 B

// ---------------- device-global prepped data ----------------
__device__ __align__(16) __nv_bfloat16 g_Bs[288 * B_LD];
__device__ float g_bb[224];
__device__ float g_sc[2];
__device__ __align__(16) __nv_bfloat16 g_AXB[(size_t)NBLK * TSTEPS * 4096];

__device__ __forceinline__ float tanha(float v) {
    float r; asm("tanh.approx.f32 %0, %1;" : "=f"(r) : "f"(v)); return r;
}
__device__ __forceinline__ uint32_t pk2(__nv_bfloat16 a, __nv_bfloat16 b) {
    return (uint32_t)__bfloat16_as_ushort(a) | ((uint32_t)__bfloat16_as_ushort(b) << 16);
}
__device__ __forceinline__ uint32_t bfsplit(float v0, float v1, uint32_t& lo) {
    __nv_bfloat16 h0 = __float2bfloat16_rn(v0);
    __nv_bfloat16 h1 = __float2bfloat16_rn(v1);
    lo = pk2(__float2bfloat16_rn(v0 - __bfloat162float(h0)),
             __float2bfloat16_rn(v1 - __bfloat162float(h1)));
    return pk2(h0, h1);
}

#define LDSM4(r0,r1,r2,r3,a) \
    asm volatile("ldmatrix.sync.aligned.m8n8.x4.shared.b16 {%0,%1,%2,%3}, [%4];" \
                 : "=r"(r0),"=r"(r1),"=r"(r2),"=r"(r3) : "r"(a))
#define LDSM4T(r0,r1,r2,r3,a) \
    asm volatile("ldmatrix.sync.aligned.m8n8.x4.trans.shared.b16 {%0,%1,%2,%3}, [%4];" \
                 : "=r"(r0),"=r"(r1),"=r"(r2),"=r"(r3) : "r"(a))
#define MMA(c0,c1,c2,c3,a0,a1,a2,a3,b0,b1) \
    asm volatile("mma.sync.aligned.m16n8k16.row.col.f32.bf16.bf16.f32 " \
                 "{%0,%1,%2,%3}, {%4,%5,%6,%7}, {%8,%9}, {%0,%1,%2,%3};" \
                 : "+f"(c0),"+f"(c1),"+f"(c2),"+f"(c3) \
                 : "r"(a0),"r"(a1),"r"(a2),"r"(a3),"r"(b0),"r"(b1))

// ---------------- setup 1: weights -> split B image (verbatim) ----------------
__global__ void setup_w(const float* __restrict__ W1, const float* __restrict__ W2,
                        const float* __restrict__ U1, const float* __restrict__ U2,
                        const float* __restrict__ bg, const float* __restrict__ bu,
                        const float* __restrict__ zeta, const float* __restrict__ nu) {
    int tid = blockIdx.x * blockDim.x + threadIdx.x;
    int nth = gridDim.x * blockDim.x;
    for (int idx = tid; idx < 288 * B_LD; idx += nth) {
        int k = idx / B_LD, n = idx % B_LD;
        float v = 0.f;
        bool lo = false;
        if (n < DH) {
            if (k < 112) {
                if (k < DH)
                    for (int r = 0; r < RU; r++) v = fmaf(U1[k * RU + r], U2[r * DH + n], v);
            } else if (k < 224) {
                int kk = k - 112; lo = true;
                if (kk < DH)
                    for (int r = 0; r < RU; r++) v = fmaf(U1[kk * RU + r], U2[r * DH + n], v);
            } else if (k < 256) {
                int kk = k - 224;
                for (int r = 0; r < RW; r++) v = fmaf(W1[kk * RW + r], W2[r * DH + n], v);
            } else {
                int kk = k - 256; lo = true;
                for (int r = 0; r < RW; r++) v = fmaf(W1[kk * RW + r], W2[r * DH + n], v);
            }
        }
        __nv_bfloat16 hi = __float2bfloat16_rn(v);
        g_Bs[idx] = lo ? __float2bfloat16_rn(v - __bfloat162float(hi)) : hi;
    }
    for (int j = tid; j < 112; j += nth) {
        g_bb[2 * j]     = (j < DH) ? bg[j] : 0.f;
        g_bb[2 * j + 1] = (j < DH) ? bu[j] : 0.f;
    }
    if (tid == 0) {
        g_sc[0] = 1.f / (1.f + expf(-zeta[0]));
        g_sc[1] = 1.f / (1.f + expf(-nu[0]));
    }
}

// ---------------- setup 2: x -> split hi/lo row images (verbatim) ----------------
__global__ void __launch_bounds__(256)
setup_x(const float* __restrict__ x) {
    int gid = blockIdx.x * 256 + threadIdx.x;
    int blk = gid / (TSTEPS * MROWS);
    int rem = gid % (TSTEPS * MROWS);
    int t = rem / MROWS, r = rem % MROWS;
    const float* xr = x + (size_t)(blk * MROWS + r) * (TSTEPS * DIN) + t * DIN;
    __nv_bfloat16 buf[64];
#pragma unroll
    for (int k = 0; k < DIN; k++) {
        float v = xr[k];
        __nv_bfloat16 hi = __float2bfloat16_rn(v);
        buf[k]      = hi;
        buf[32 + k] = __float2bfloat16_rn(v - __bfloat162float(hi));
    }
    uint4* dst = (uint4*)(g_AXB + ((size_t)(blk * TSTEPS + t)) * 4096 + r * 64);
    const uint4* src = (const uint4*)buf;
#pragma unroll
    for (int i = 0; i < 8; i++) dst[i] = src[i];
}

// ---------------- persistent raw-MMA recurrent kernel, pipelined ----------------
__global__ void __launch_bounds__(NTHR)
grnn_kernel(const float* __restrict__ FC, const float* __restrict__ FCb,
            float* __restrict__ out) {
    extern __shared__ __align__(16) char sm[];
    __nv_bfloat16* As = (__nv_bfloat16*)(sm + SM_A);     // double buffered
    __nv_bfloat16* Bs = (__nv_bfloat16*)(sm + SM_B);
    float2* bbs = (float2*)(sm + SM_BB);
    float*  scr = (float*)(sm + SM_SCR);

    const int tid = threadIdx.x;
    const int blk = blockIdx.x;

    // ---- init: B copy, A[0] zero + x(0), biases ----
    {
        uint4* d = (uint4*)Bs; const uint4* s = (const uint4*)g_Bs;
        for (int i = tid; i < B_BYTES / 16; i += NTHR) d[i] = s[i];
        d = (uint4*)As;
        for (int i = tid; i < A_BYTES / 16; i += NTHR) d[i] = make_uint4(0, 0, 0, 0);
        const uint4* xs0 = (const uint4*)(g_AXB + (size_t)blk * TSTEPS * 4096);
        for (int i = tid; i < 512; i += NTHR)
            *(uint4*)((char*)As + (i >> 3) * (A_LD * 2) + 448 + (i & 7) * 16) = xs0[i];
        for (int j = tid; j < 112; j += NTHR)
            bbs[j] = make_float2(g_bb[2 * j], g_bb[2 * j + 1]);
    }
    __syncthreads();

    const float sz = g_sc[0];
    const float sn = g_sc[1];

    const int w    = tid >> 5;
    const int lane = tid & 31;
    const int wm   = w & 1;
    const int wn   = w >> 1;
    const int g    = lane >> 2;
    const int tg   = lane & 3;
    const int lm   = lane >> 3;
    const int lr   = lane & 7;

    uint32_t As32 = (uint32_t)__cvta_generic_to_shared(As);
    uint32_t Bs32 = (uint32_t)__cvta_generic_to_shared(Bs);
    const uint32_t aLane = (uint32_t)(((32 * wm + lr + ((lm & 1) << 3)) * A_LD + ((lm >> 1) << 3)) * 2);
    const uint32_t bAddr = Bs32 + (uint32_t)(((lr + ((lm & 1) << 3)) * B_LD + 16 * wn + ((lm >> 1) << 3)) * 2);

    // biases
    float bgv[2][2], buv[2][2];
#pragma unroll
    for (int ni = 0; ni < 2; ni++)
#pragma unroll
        for (int e = 0; e < 2; e++) {
            float2 bb = bbs[16 * wn + 8 * ni + 2 * tg + e];
            bgv[ni][e] = bb.x; buv[ni][e] = bb.y;
        }

    float H[2][2][4];
#pragma unroll
    for (int mi = 0; mi < 2; mi++)
#pragma unroll
        for (int ni = 0; ni < 2; ni++)
#pragma unroll
            for (int e = 0; e < 4; e++) H[mi][ni][e] = 0.f;

    // per-unit byte offsets (u = 0..6 H k-units, u = 7..8 x k-units)
    // A: hi offset, lo offset relative to aAddr; B likewise relative to bAddr.
#define OFF_AH(u)  ((u) < 7 ? (u) * 32 : 448 + 32 * ((u) - 7))
#define OFF_AL(u)  ((u) < 7 ? OFF_AH(u) + 224 : OFF_AH(u) + 64)
#define OFF_BH(u)  ((u) < 7 ? (u) * 16 * B_LD * 2 : (224 + 16 * ((u) - 7)) * B_LD * 2)
#define OFF_BL(u)  ((u) < 7 ? OFF_BH(u) + 112 * B_LD * 2 : OFF_BH(u) + 32 * B_LD * 2)

    int p = 0;
    for (int t = 0; t < TSTEPS; t++) {
        // prefetch next step's x rows
        uint4 xp0, xp1;
        const int hx = (t + 1 < TSTEPS);
        if (hx) {
            const uint4* s = (const uint4*)(g_AXB + (size_t)(blk * TSTEPS + t + 1) * 4096);
            xp0 = s[tid];
            if (tid < 64) xp1 = s[tid + NTHR];
        }

        const uint32_t aAddr0 = As32 + p * A_BYTES + aLane;
        const uint32_t aAddr1 = aAddr0 + 16 * A_LD * 2;

        float c[2][2][4];
#pragma unroll
        for (int mi = 0; mi < 2; mi++)
#pragma unroll
            for (int ni = 0; ni < 2; ni++)
#pragma unroll
                for (int e = 0; e < 4; e++) c[mi][ni][e] = 0.f;

        // ---- 9 uniform units, 2-stage register pipeline ----
        uint32_t Af[2][2][8];   // [stage][mi][frag: 0-3 hi, 4-7 lo]
        uint32_t Bf[2][8];      // [stage][frag: 0-3 hi, 4-7 lo]

        // preload unit 0 into stage 0
        LDSM4(Af[0][0][0], Af[0][0][1], Af[0][0][2], Af[0][0][3], aAddr0 + OFF_AH(0));
        LDSM4(Af[0][0][4], Af[0][0][5], Af[0][0][6], Af[0][0][7], aAddr0 + OFF_AL(0));
        LDSM4(Af[0][1][0], Af[0][1][1], Af[0][1][2], Af[0][1][3], aAddr1 + OFF_AH(0));
        LDSM4(Af[0][1][4], Af[0][1][5], Af[0][1][6], Af[0][1][7], aAddr1 + OFF_AL(0));
        LDSM4T(Bf[0][0], Bf[0][1], Bf[0][2], Bf[0][3], bAddr + OFF_BH(0));
        LDSM4T(Bf[0][4], Bf[0][5], Bf[0][6], Bf[0][7], bAddr + OFF_BL(0));

#pragma unroll
        for (int u = 0; u < 9; u++) {
            const int cu = u & 1;
            const int nx = cu ^ 1;
            if (u < 8) {
                const int v = u + 1;
                LDSM4(Af[nx][0][0], Af[nx][0][1], Af[nx][0][2], Af[nx][0][3], aAddr0 + OFF_AH(v));
                LDSM4(Af[nx][0][4], Af[nx][0][5], Af[nx][0][6], Af[nx][0][7], aAddr0 + OFF_AL(v));
                LDSM4(Af[nx][1][0], Af[nx][1][1], Af[nx][1][2], Af[nx][1][3], aAddr1 + OFF_AH(v));
                LDSM4(Af[nx][1][4], Af[nx][1][5], Af[nx][1][6], Af[nx][1][7], aAddr1 + OFF_AL(v));
                LDSM4T(Bf[nx][0], Bf[nx][1], Bf[nx][2], Bf[nx][3], bAddr + OFF_BH(v));
                LDSM4T(Bf[nx][4], Bf[nx][5], Bf[nx][6], Bf[nx][7], bAddr + OFF_BL(v));
            }
#pragma unroll
            for (int mi = 0; mi < 2; mi++) {
                MMA(c[mi][0][0], c[mi][0][1], c[mi][0][2], c[mi][0][3],
                    Af[cu][mi][0], Af[cu][mi][1], Af[cu][mi][2], Af[cu][mi][3], Bf[cu][0], Bf[cu][1]);
                MMA(c[mi][1][0], c[mi][1][1], c[mi][1][2], c[mi][1][3],
                    Af[cu][mi][0], Af[cu][mi][1], Af[cu][mi][2], Af[cu][mi][3], Bf[cu][2], Bf[cu][3]);
                MMA(c[mi][0][0], c[mi][0][1], c[mi][0][2], c[mi][0][3],
                    Af[cu][mi][4], Af[cu][mi][5], Af[cu][mi][6], Af[cu][mi][7], Bf[cu][0], Bf[cu][1]);
                MMA(c[mi][1][0], c[mi][1][1], c[mi][1][2], c[mi][1][3],
                    Af[cu][mi][4], Af[cu][mi][5], Af[cu][mi][6], Af[cu][mi][7], Bf[cu][2], Bf[cu][3]);
                MMA(c[mi][0][0], c[mi][0][1], c[mi][0][2], c[mi][0][3],
                    Af[cu][mi][0], Af[cu][mi][1], Af[cu][mi][2], Af[cu][mi][3], Bf[cu][4], Bf[cu][5]);
                MMA(c[mi][1][0], c[mi][1][1], c[mi][1][2], c[mi][1][3],
                    Af[cu][mi][0], Af[cu][mi][1], Af[cu][mi][2], Af[cu][mi][3], Bf[cu][6], Bf[cu][7]);
            }
        }

        // ---- in-register gate epilogue ----
#pragma unroll
        for (int mi = 0; mi < 2; mi++)
#pragma unroll
            for (int ni = 0; ni < 2; ni++) {
                int col0 = 16 * wn + 8 * ni + 2 * tg;
#pragma unroll
                for (int e = 0; e < 4; e++) {
                    int ee = e & 1;
                    float cc = c[mi][ni][e];
                    float gg = fmaf(0.5f, tanha(0.5f * (cc + bgv[ni][ee])), 0.5f);
                    float hh = tanha(cc + buv[ni][ee]);
                    float hn = fmaf(gg, H[mi][ni][e] - sz, fmaf(sn, hh, sz));
                    H[mi][ni][e] = (col0 + ee < DH) ? hn : 0.f;
                }
            }

        // ---- write H + x into the OTHER buffer ----
        char* Aw = (char*)As + (p ^ 1) * A_BYTES;
#pragma unroll
        for (int mi = 0; mi < 2; mi++) {
            int r0 = 32 * wm + 16 * mi + g;
#pragma unroll
            for (int ni = 0; ni < 2; ni++) {
                int col0 = 16 * wn + 8 * ni + 2 * tg;
                uint32_t lo0, lo1;
                uint32_t hi0 = bfsplit(H[mi][ni][0], H[mi][ni][1], lo0);
                uint32_t hi1 = bfsplit(H[mi][ni][2], H[mi][ni][3], lo1);
                char* p0 = Aw + (r0 * A_LD + col0) * 2;
                char* p1 = Aw + ((r0 + 8) * A_LD + col0) * 2;
                *(uint32_t*)p0 = hi0;  *(uint32_t*)(p0 + 224) = lo0;
                *(uint32_t*)p1 = hi1;  *(uint32_t*)(p1 + 224) = lo1;
            }
        }
        if (hx) {
            *(uint4*)(Aw + (tid >> 3) * (A_LD * 2) + 448 + (tid & 7) * 16) = xp0;
            if (tid < 64) {
                int i = tid + NTHR;
                *(uint4*)(Aw + (i >> 3) * (A_LD * 2) + 448 + (i & 7) * 16) = xp1;
            }
        }
        __syncthreads();
        p ^= 1;
    }

    // ---- scores ----
    for (int i = tid; i < MROWS * NCLS; i += NTHR) scr[i] = 0.f;
    __syncthreads();
#pragma unroll
    for (int mi = 0; mi < 2; mi++)
#pragma unroll
        for (int half = 0; half < 2; half++) {
            int row = 32 * wm + 16 * mi + g + 8 * half;
            float s[NCLS];
#pragma unroll
            for (int cix = 0; cix < NCLS; cix++) s[cix] = 0.f;
#pragma unroll
            for (int ni = 0; ni < 2; ni++)
#pragma unroll
                for (int e = 0; e < 2; e++) {
                    int col = 16 * wn + 8 * ni + 2 * tg + e;
                    if (col < DH) {
                        float hv = H[mi][ni][2 * half + e];
#pragma unroll
                        for (int cix = 0; cix < NCLS; cix++)
                            s[cix] = fmaf(hv, __ldg(FC + col * NCLS + cix), s[cix]);
                    }
                }
#pragma unroll
            for (int cix = 0; cix < NCLS; cix++)
                atomicAdd(&scr[row * NCLS + cix], s[cix]);
        }
    __syncthreads();
    if (tid < MROWS) {
        int grow = blk * MROWS + tid;
#pragma unroll
        for (int cix = 0; cix < NCLS; cix++)
            out[(size_t)grow * NCLS + cix] = scr[tid * NCLS + cix] + __ldg(FCb + cix);
    }
}

// ---------------- launch ----------------
extern "C" void kernel_launch(void* const* d_in, const int* in_sizes, int n_in,
                              void* d_out, int out_size) {
    const float* x    = (const float*)d_in[0];
    const float* W1   = (const float*)d_in[1];
    const float* W2   = (const float*)d_in[2];
    const float* U1   = (const float*)d_in[3];
    const float* U2   = (const float*)d_in[4];
    const float* bg   = (const float*)d_in[5];
    const float* bu   = (const float*)d_in[6];
    const float* zeta = (const float*)d_in[7];
    const float* nu   = (const float*)d_in[8];
    const float* FC   = (const float*)d_in[9];
    const float* FCb  = (const float*)d_in[10];
    float* out = (float*)d_out;

    cudaFuncSetAttribute(grnn_kernel, cudaFuncAttributeMaxDynamicSharedMemorySize, SM_TOT);

    setup_w<<<16, 256>>>(W1, W2, U1, U2, bg, bu, zeta, nu);
    setup_x<<<(NBLK * TSTEPS * MROWS) / 256, 256>>>(x);
    grnn_kernel<<<NBLK, NTHR, SM_TOT>>>(FC, FCb, out);
}

// round 15
// speedup vs baseline: 1.1170x; 1.1170x over previous
#include <cuda_runtime.h>
#include <cuda_bf16.h>
#include <math.h>
#include <stdint.h>

// ---------------- problem constants ----------------
#define BATCH   8192
#define TSTEPS  99
#define DIN     32
#define DH      100
#define RW      16
#define RU      25
#define NCLS    6
#define MROWS   64
#define NBLK    (BATCH / MROWS)      // 128
#define NTHR    448                  // 14 warps: 2(m) x 7(n)

// A: 64 x 296 bf16. cols: 0-111 Hhi, 112-223 Hlo, 224-255 xhi, 256-287 xlo
#define A_LD    296
#define A_BYTES (64 * A_LD * 2)      // 37888
// B: 288 x 136 bf16. rows: 0-111 Uhi, 112-223 Ulo, 224-255 Whi, 256-287 Wlo
#define B_LD    136
#define B_BYTES (288 * B_LD * 2)     // 78336

#define SM_A    0                    // double buffered: A[0], A[1]
#define SM_B    (SM_A + 2 * A_BYTES)
#define SM_BB   (SM_B + B_BYTES)
#define SM_SCR  (SM_BB + 1024)
#define SM_TOT  (SM_SCR + 1536)      // 156672 B

// ---------------- device-global prepped data ----------------
__device__ __align__(16) __nv_bfloat16 g_Bs[288 * B_LD];
__device__ float g_bb[224];
__device__ float g_sc[2];

__device__ __forceinline__ float tanha(float v) {
    float r; asm("tanh.approx.f32 %0, %1;" : "=f"(r) : "f"(v)); return r;
}
__device__ __forceinline__ uint32_t pk2(__nv_bfloat16 a, __nv_bfloat16 b) {
    return (uint32_t)__bfloat16_as_ushort(a) | ((uint32_t)__bfloat16_as_ushort(b) << 16);
}
__device__ __forceinline__ uint32_t bfsplit(float v0, float v1, uint32_t& lo) {
    __nv_bfloat16 h0 = __float2bfloat16_rn(v0);
    __nv_bfloat16 h1 = __float2bfloat16_rn(v1);
    lo = pk2(__float2bfloat16_rn(v0 - __bfloat162float(h0)),
             __float2bfloat16_rn(v1 - __bfloat162float(h1)));
    return pk2(h0, h1);
}
// split a float4 (cols c..c+3) into hi/lo packed pairs
__device__ __forceinline__ void split4(float4 f, uint2& hi, uint2& lo) {
    uint32_t l01, l23;
    uint32_t h01 = bfsplit(f.x, f.y, l01);
    uint32_t h23 = bfsplit(f.z, f.w, l23);
    hi = make_uint2(h01, h23);
    lo = make_uint2(l01, l23);
}

#define LDSM4(r0,r1,r2,r3,a) \
    asm volatile("ldmatrix.sync.aligned.m8n8.x4.shared.b16 {%0,%1,%2,%3}, [%4];" \
                 : "=r"(r0),"=r"(r1),"=r"(r2),"=r"(r3) : "r"(a))
#define LDSM4T(r0,r1,r2,r3,a) \
    asm volatile("ldmatrix.sync.aligned.m8n8.x4.trans.shared.b16 {%0,%1,%2,%3}, [%4];" \
                 : "=r"(r0),"=r"(r1),"=r"(r2),"=r"(r3) : "r"(a))
#define MMA(c0,c1,c2,c3,a0,a1,a2,a3,b0,b1) \
    asm volatile("mma.sync.aligned.m16n8k16.row.col.f32.bf16.bf16.f32 " \
                 "{%0,%1,%2,%3}, {%4,%5,%6,%7}, {%8,%9}, {%0,%1,%2,%3};" \
                 : "+f"(c0),"+f"(c1),"+f"(c2),"+f"(c3) \
                 : "r"(a0),"r"(a1),"r"(a2),"r"(a3),"r"(b0),"r"(b1))

// ---------------- setup: weights -> split B image (verbatim) ----------------
__global__ void setup_w(const float* __restrict__ W1, const float* __restrict__ W2,
                        const float* __restrict__ U1, const float* __restrict__ U2,
                        const float* __restrict__ bg, const float* __restrict__ bu,
                        const float* __restrict__ zeta, const float* __restrict__ nu) {
    int tid = blockIdx.x * blockDim.x + threadIdx.x;
    int nth = gridDim.x * blockDim.x;
    for (int idx = tid; idx < 288 * B_LD; idx += nth) {
        int k = idx / B_LD, n = idx % B_LD;
        float v = 0.f;
        bool lo = false;
        if (n < DH) {
            if (k < 112) {
                if (k < DH)
                    for (int r = 0; r < RU; r++) v = fmaf(U1[k * RU + r], U2[r * DH + n], v);
            } else if (k < 224) {
                int kk = k - 112; lo = true;
                if (kk < DH)
                    for (int r = 0; r < RU; r++) v = fmaf(U1[kk * RU + r], U2[r * DH + n], v);
            } else if (k < 256) {
                int kk = k - 224;
                for (int r = 0; r < RW; r++) v = fmaf(W1[kk * RW + r], W2[r * DH + n], v);
            } else {
                int kk = k - 256; lo = true;
                for (int r = 0; r < RW; r++) v = fmaf(W1[kk * RW + r], W2[r * DH + n], v);
            }
        }
        __nv_bfloat16 hi = __float2bfloat16_rn(v);
        g_Bs[idx] = lo ? __float2bfloat16_rn(v - __bfloat162float(hi)) : hi;
    }
    for (int j = tid; j < 112; j += nth) {
        g_bb[2 * j]     = (j < DH) ? bg[j] : 0.f;
        g_bb[2 * j + 1] = (j < DH) ? bu[j] : 0.f;
    }
    if (tid == 0) {
        g_sc[0] = 1.f / (1.f + expf(-zeta[0]));
        g_sc[1] = 1.f / (1.f + expf(-nu[0]));
    }
}

// ---------------- persistent raw-MMA recurrent kernel ----------------
__global__ void __launch_bounds__(NTHR)
grnn_kernel(const float* __restrict__ x, const float* __restrict__ FC,
            const float* __restrict__ FCb, float* __restrict__ out) {
    extern __shared__ __align__(16) char sm[];
    __nv_bfloat16* As = (__nv_bfloat16*)(sm + SM_A);     // double buffered
    __nv_bfloat16* Bs = (__nv_bfloat16*)(sm + SM_B);
    float2* bbs = (float2*)(sm + SM_BB);
    float*  scr = (float*)(sm + SM_SCR);

    const int tid = threadIdx.x;
    const int blk = blockIdx.x;

    // x-chunk assignment: chunk idx covers (row = idx>>3, 4 floats at col (idx&7)*4)
    const int xr0i = tid >> 3;
    const int xo0  = tid & 7;
    const float* xbase0 = x + (size_t)(blk * MROWS + xr0i) * (TSTEPS * DIN) + xo0 * 4;
    const int xi1  = tid + NTHR;              // second chunk for tid<64
    const float* xbase1 = x + (size_t)(blk * MROWS + (xi1 >> 3)) * (TSTEPS * DIN) + (xi1 & 7) * 4;

    // ---- init: B copy, A[0] zero + x(0) split, biases ----
    {
        uint4* d = (uint4*)Bs; const uint4* s = (const uint4*)g_Bs;
        for (int i = tid; i < B_BYTES / 16; i += NTHR) d[i] = s[i];
        d = (uint4*)As;
        for (int i = tid; i < A_BYTES / 16; i += NTHR) d[i] = make_uint4(0, 0, 0, 0);
        for (int j = tid; j < 112; j += NTHR)
            bbs[j] = make_float2(g_bb[2 * j], g_bb[2 * j + 1]);
        // stage t=0 x
        {
            float4 f = *(const float4*)xbase0;
            uint2 hi, lo; split4(f, hi, lo);
            char* r = (char*)As + xr0i * (A_LD * 2);
            *(uint2*)(r + 448 + xo0 * 8) = hi;
            *(uint2*)(r + 512 + xo0 * 8) = lo;
        }
        if (tid < 64) {
            float4 f = *(const float4*)xbase1;
            uint2 hi, lo; split4(f, hi, lo);
            char* r = (char*)As + (xi1 >> 3) * (A_LD * 2);
            *(uint2*)(r + 448 + (xi1 & 7) * 8) = hi;
            *(uint2*)(r + 512 + (xi1 & 7) * 8) = lo;
        }
    }
    __syncthreads();

    const float sz = g_sc[0];
    const float sn = g_sc[1];

    const int w    = tid >> 5;
    const int lane = tid & 31;
    const int wm   = w & 1;
    const int wn   = w >> 1;
    const int g    = lane >> 2;
    const int tg   = lane & 3;
    const int lm   = lane >> 3;
    const int lr   = lane & 7;

    uint32_t As32 = (uint32_t)__cvta_generic_to_shared(As);
    uint32_t Bs32 = (uint32_t)__cvta_generic_to_shared(Bs);
    const uint32_t aLane = (uint32_t)(((32 * wm + lr + ((lm & 1) << 3)) * A_LD + ((lm >> 1) << 3)) * 2);
    const uint32_t bAddr = Bs32 + (uint32_t)(((lr + ((lm & 1) << 3)) * B_LD + 16 * wn + ((lm >> 1) << 3)) * 2);

    // ---- hoist ALL B fragments into registers (constant across steps) ----
    uint32_t BH[7][8], BX[2][8];
#pragma unroll
    for (int kk = 0; kk < 7; kk++) {
        uint32_t kb = bAddr + kk * 16 * B_LD * 2;
        LDSM4T(BH[kk][0], BH[kk][1], BH[kk][2], BH[kk][3], kb);
        LDSM4T(BH[kk][4], BH[kk][5], BH[kk][6], BH[kk][7], kb + 112 * B_LD * 2);
    }
#pragma unroll
    for (int kk = 0; kk < 2; kk++) {
        uint32_t kb = bAddr + (224 + 16 * kk) * B_LD * 2;
        LDSM4T(BX[kk][0], BX[kk][1], BX[kk][2], BX[kk][3], kb);
        LDSM4T(BX[kk][4], BX[kk][5], BX[kk][6], BX[kk][7], kb + 32 * B_LD * 2);
    }

    // biases
    float bgv[2][2], buv[2][2];
#pragma unroll
    for (int ni = 0; ni < 2; ni++)
#pragma unroll
        for (int e = 0; e < 2; e++) {
            float2 bb = bbs[16 * wn + 8 * ni + 2 * tg + e];
            bgv[ni][e] = bb.x; buv[ni][e] = bb.y;
        }

    float H[2][2][4];
#pragma unroll
    for (int mi = 0; mi < 2; mi++)
#pragma unroll
        for (int ni = 0; ni < 2; ni++)
#pragma unroll
            for (int e = 0; e < 4; e++) H[mi][ni][e] = 0.f;

    int p = 0;
    for (int t = 0; t < TSTEPS; t++) {
        // prefetch next step's RAW x (fp32, coalesced)
        float4 xp0, xp1;
        const int hx = (t + 1 < TSTEPS);
        if (hx) {
            xp0 = *(const float4*)(xbase0 + (t + 1) * DIN);
            if (tid < 64) xp1 = *(const float4*)(xbase1 + (t + 1) * DIN);
        }

        const uint32_t aAddr0 = As32 + p * A_BYTES + aLane;
        const uint32_t aAddr1 = aAddr0 + 16 * A_LD * 2;

        float c[2][2][4];
#pragma unroll
        for (int mi = 0; mi < 2; mi++)
#pragma unroll
            for (int ni = 0; ni < 2; ni++)
#pragma unroll
                for (int e = 0; e < 4; e++) c[mi][ni][e] = 0.f;

        // ---- H part: 7 k-units ----
#pragma unroll
        for (int kk = 0; kk < 7; kk++) {
#pragma unroll
            for (int mi = 0; mi < 2; mi++) {
                uint32_t ka = (mi ? aAddr1 : aAddr0) + kk * 32;
                uint32_t a0, a1, a2, a3, l0, l1, l2, l3;
                LDSM4(a0, a1, a2, a3, ka);
                LDSM4(l0, l1, l2, l3, ka + 224);
                MMA(c[mi][0][0], c[mi][0][1], c[mi][0][2], c[mi][0][3], a0, a1, a2, a3, BH[kk][0], BH[kk][1]);
                MMA(c[mi][1][0], c[mi][1][1], c[mi][1][2], c[mi][1][3], a0, a1, a2, a3, BH[kk][2], BH[kk][3]);
                MMA(c[mi][0][0], c[mi][0][1], c[mi][0][2], c[mi][0][3], l0, l1, l2, l3, BH[kk][0], BH[kk][1]);
                MMA(c[mi][1][0], c[mi][1][1], c[mi][1][2], c[mi][1][3], l0, l1, l2, l3, BH[kk][2], BH[kk][3]);
                MMA(c[mi][0][0], c[mi][0][1], c[mi][0][2], c[mi][0][3], a0, a1, a2, a3, BH[kk][4], BH[kk][5]);
                MMA(c[mi][1][0], c[mi][1][1], c[mi][1][2], c[mi][1][3], a0, a1, a2, a3, BH[kk][6], BH[kk][7]);
            }
        }
        // ---- x part: 2 k-units ----
#pragma unroll
        for (int kk = 0; kk < 2; kk++) {
#pragma unroll
            for (int mi = 0; mi < 2; mi++) {
                uint32_t ka = (mi ? aAddr1 : aAddr0) + (224 + 16 * kk) * 2;
                uint32_t a0, a1, a2, a3, l0, l1, l2, l3;
                LDSM4(a0, a1, a2, a3, ka);
                LDSM4(l0, l1, l2, l3, ka + 64);
                MMA(c[mi][0][0], c[mi][0][1], c[mi][0][2], c[mi][0][3], a0, a1, a2, a3, BX[kk][0], BX[kk][1]);
                MMA(c[mi][1][0], c[mi][1][1], c[mi][1][2], c[mi][1][3], a0, a1, a2, a3, BX[kk][2], BX[kk][3]);
                MMA(c[mi][0][0], c[mi][0][1], c[mi][0][2], c[mi][0][3], l0, l1, l2, l3, BX[kk][0], BX[kk][1]);
                MMA(c[mi][1][0], c[mi][1][1], c[mi][1][2], c[mi][1][3], l0, l1, l2, l3, BX[kk][2], BX[kk][3]);
                MMA(c[mi][0][0], c[mi][0][1], c[mi][0][2], c[mi][0][3], a0, a1, a2, a3, BX[kk][4], BX[kk][5]);
                MMA(c[mi][1][0], c[mi][1][1], c[mi][1][2], c[mi][1][3], a0, a1, a2, a3, BX[kk][6], BX[kk][7]);
            }
        }

        // ---- in-register gate epilogue ----
#pragma unroll
        for (int mi = 0; mi < 2; mi++)
#pragma unroll
            for (int ni = 0; ni < 2; ni++) {
                int col0 = 16 * wn + 8 * ni + 2 * tg;
#pragma unroll
                for (int e = 0; e < 4; e++) {
                    int ee = e & 1;
                    float cc = c[mi][ni][e];
                    float gg = fmaf(0.5f, tanha(0.5f * (cc + bgv[ni][ee])), 0.5f);
                    float hh = tanha(cc + buv[ni][ee]);
                    float hn = fmaf(gg, H[mi][ni][e] - sz, fmaf(sn, hh, sz));
                    H[mi][ni][e] = (col0 + ee < DH) ? hn : 0.f;
                }
            }

        // ---- write H + split x into the OTHER buffer ----
        char* Aw = (char*)As + (p ^ 1) * A_BYTES;
#pragma unroll
        for (int mi = 0; mi < 2; mi++) {
            int r0 = 32 * wm + 16 * mi + g;
#pragma unroll
            for (int ni = 0; ni < 2; ni++) {
                int col0 = 16 * wn + 8 * ni + 2 * tg;
                uint32_t lo0, lo1;
                uint32_t hi0 = bfsplit(H[mi][ni][0], H[mi][ni][1], lo0);
                uint32_t hi1 = bfsplit(H[mi][ni][2], H[mi][ni][3], lo1);
                char* p0 = Aw + (r0 * A_LD + col0) * 2;
                char* p1 = Aw + ((r0 + 8) * A_LD + col0) * 2;
                *(uint32_t*)p0 = hi0;  *(uint32_t*)(p0 + 224) = lo0;
                *(uint32_t*)p1 = hi1;  *(uint32_t*)(p1 + 224) = lo1;
            }
        }
        if (hx) {
            {
                uint2 hi, lo; split4(xp0, hi, lo);
                char* r = Aw + xr0i * (A_LD * 2);
                *(uint2*)(r + 448 + xo0 * 8) = hi;
                *(uint2*)(r + 512 + xo0 * 8) = lo;
            }
            if (tid < 64) {
                uint2 hi, lo; split4(xp1, hi, lo);
                char* r = Aw + (xi1 >> 3) * (A_LD * 2);
                *(uint2*)(r + 448 + (xi1 & 7) * 8) = hi;
                *(uint2*)(r + 512 + (xi1 & 7) * 8) = lo;
            }
        }
        __syncthreads();
        p ^= 1;
    }

    // ---- scores ----
    for (int i = tid; i < MROWS * NCLS; i += NTHR) scr[i] = 0.f;
    __syncthreads();
#pragma unroll
    for (int mi = 0; mi < 2; mi++)
#pragma unroll
        for (int half = 0; half < 2; half++) {
            int row = 32 * wm + 16 * mi + g + 8 * half;
            float s[NCLS];
#pragma unroll
            for (int cix = 0; cix < NCLS; cix++) s[cix] = 0.f;
#pragma unroll
            for (int ni = 0; ni < 2; ni++)
#pragma unroll
                for (int e = 0; e < 2; e++) {
                    int col = 16 * wn + 8 * ni + 2 * tg + e;
                    if (col < DH) {
                        float hv = H[mi][ni][2 * half + e];
#pragma unroll
                        for (int cix = 0; cix < NCLS; cix++)
                            s[cix] = fmaf(hv, __ldg(FC + col * NCLS + cix), s[cix]);
                    }
                }
#pragma unroll
            for (int cix = 0; cix < NCLS; cix++)
                atomicAdd(&scr[row * NCLS + cix], s[cix]);
        }
    __syncthreads();
    if (tid < MROWS) {
        int grow = blk * MROWS + tid;
#pragma unroll
        for (int cix = 0; cix < NCLS; cix++)
            out[(size_t)grow * NCLS + cix] = scr[tid * NCLS + cix] + __ldg(FCb + cix);
    }
}

// ---------------- launch ----------------
extern "C" void kernel_launch(void* const* d_in, const int* in_sizes, int n_in,
                              void* d_out, int out_size) {
    const float* x    = (const float*)d_in[0];
    const float* W1   = (const float*)d_in[1];
    const float* W2   = (const float*)d_in[2];
    const float* U1   = (const float*)d_in[3];
    const float* U2   = (const float*)d_in[4];
    const float* bg   = (const float*)d_in[5];
    const float* bu   = (const float*)d_in[6];
    const float* zeta = (const float*)d_in[7];
    const float* nu   = (const float*)d_in[8];
    const float* FC   = (const float*)d_in[9];
    const float* FCb  = (const float*)d_in[10];
    float* out = (float*)d_out;

    cudaFuncSetAttribute(grnn_kernel, cudaFuncAttributeMaxDynamicSharedMemorySize, SM_TOT);

    setup_w<<<16, 256>>>(W1, W2, U1, U2, bg, bu, zeta, nu);
    grnn_kernel<<<NBLK, NTHR, SM_TOT>>>(x, FC, FCb, out);
}

// round 16
// speedup vs baseline: 1.3266x; 1.1876x over previous
#include <cuda_runtime.h>
#include <cuda_bf16.h>
#include <math.h>
#include <stdint.h>

// ---------------- problem constants ----------------
#define BATCH   8192
#define TSTEPS  99
#define DIN     32
#define DH      100
#define RW      16
#define RU      25
#define NCLS    6
#define MROWS   64
#define NBLK    (BATCH / MROWS)      // 128
#define NTHR    896                  // 28 warps: 4(m) x 7(n)

// A: 64 x 296 bf16. cols: 0-111 Hhi, 112-223 Hlo, 224-255 xhi, 256-287 xlo
#define A_LD    296
#define A_BYTES (64 * A_LD * 2)      // 37888
// B: 288 x 136 bf16. rows: 0-111 Uhi, 112-223 Ulo, 224-255 Whi, 256-287 Wlo
#define B_LD    136
#define B_BYTES (288 * B_LD * 2)     // 78336

#define SM_A    0                    // double buffered: A[0], A[1]
#define SM_B    (SM_A + 2 * A_BYTES)
#define SM_BB   (SM_B + B_BYTES)
#define SM_SCR  (SM_BB + 1024)
#define SM_TOT  (SM_SCR + 1536)      // 156672 B

// ---------------- device-global prepped data ----------------
__device__ __align__(16) __nv_bfloat16 g_Bs[288 * B_LD];
__device__ float g_bb[224];
__device__ float g_sc[2];

__device__ __forceinline__ float tanha(float v) {
    float r; asm("tanh.approx.f32 %0, %1;" : "=f"(r) : "f"(v)); return r;
}
__device__ __forceinline__ uint32_t pk2(__nv_bfloat16 a, __nv_bfloat16 b) {
    return (uint32_t)__bfloat16_as_ushort(a) | ((uint32_t)__bfloat16_as_ushort(b) << 16);
}
__device__ __forceinline__ uint32_t bfsplit(float v0, float v1, uint32_t& lo) {
    __nv_bfloat16 h0 = __float2bfloat16_rn(v0);
    __nv_bfloat16 h1 = __float2bfloat16_rn(v1);
    lo = pk2(__float2bfloat16_rn(v0 - __bfloat162float(h0)),
             __float2bfloat16_rn(v1 - __bfloat162float(h1)));
    return pk2(h0, h1);
}
__device__ __forceinline__ void split4(float4 f, uint2& hi, uint2& lo) {
    uint32_t l01, l23;
    uint32_t h01 = bfsplit(f.x, f.y, l01);
    uint32_t h23 = bfsplit(f.z, f.w, l23);
    hi = make_uint2(h01, h23);
    lo = make_uint2(l01, l23);
}

#define LDSM4(r0,r1,r2,r3,a) \
    asm volatile("ldmatrix.sync.aligned.m8n8.x4.shared.b16 {%0,%1,%2,%3}, [%4];" \
                 : "=r"(r0),"=r"(r1),"=r"(r2),"=r"(r3) : "r"(a))
#define LDSM4T(r0,r1,r2,r3,a) \
    asm volatile("ldmatrix.sync.aligned.m8n8.x4.trans.shared.b16 {%0,%1,%2,%3}, [%4];" \
                 : "=r"(r0),"=r"(r1),"=r"(r2),"=r"(r3) : "r"(a))
#define MMA(c0,c1,c2,c3,a0,a1,a2,a3,b0,b1) \
    asm volatile("mma.sync.aligned.m16n8k16.row.col.f32.bf16.bf16.f32 " \
                 "{%0,%1,%2,%3}, {%4,%5,%6,%7}, {%8,%9}, {%0,%1,%2,%3};" \
                 : "+f"(c0),"+f"(c1),"+f"(c2),"+f"(c3) \
                 : "r"(a0),"r"(a1),"r"(a2),"r"(a3),"r"(b0),"r"(b1))

// per-unit byte offsets (u = 0..6 H k-units, u = 7..8 x k-units)
#define OFF_AH(u)  ((u) < 7 ? (u) * 32 : 448 + 32 * ((u) - 7))
#define OFF_ALD(u) ((u) < 7 ? 224 : 64)
#define OFF_BH(u)  ((u) < 7 ? (u) * 16 * B_LD * 2 : (224 + 16 * ((u) - 7)) * B_LD * 2)
#define OFF_BLD(u) ((u) < 7 ? 112 * B_LD * 2 : 32 * B_LD * 2)

// ---------------- setup: weights -> split B image (verbatim) ----------------
__global__ void setup_w(const float* __restrict__ W1, const float* __restrict__ W2,
                        const float* __restrict__ U1, const float* __restrict__ U2,
                        const float* __restrict__ bg, const float* __restrict__ bu,
                        const float* __restrict__ zeta, const float* __restrict__ nu) {
    int tid = blockIdx.x * blockDim.x + threadIdx.x;
    int nth = gridDim.x * blockDim.x;
    for (int idx = tid; idx < 288 * B_LD; idx += nth) {
        int k = idx / B_LD, n = idx % B_LD;
        float v = 0.f;
        bool lo = false;
        if (n < DH) {
            if (k < 112) {
                if (k < DH)
                    for (int r = 0; r < RU; r++) v = fmaf(U1[k * RU + r], U2[r * DH + n], v);
            } else if (k < 224) {
                int kk = k - 112; lo = true;
                if (kk < DH)
                    for (int r = 0; r < RU; r++) v = fmaf(U1[kk * RU + r], U2[r * DH + n], v);
            } else if (k < 256) {
                int kk = k - 224;
                for (int r = 0; r < RW; r++) v = fmaf(W1[kk * RW + r], W2[r * DH + n], v);
            } else {
                int kk = k - 256; lo = true;
                for (int r = 0; r < RW; r++) v = fmaf(W1[kk * RW + r], W2[r * DH + n], v);
            }
        }
        __nv_bfloat16 hi = __float2bfloat16_rn(v);
        g_Bs[idx] = lo ? __float2bfloat16_rn(v - __bfloat162float(hi)) : hi;
    }
    for (int j = tid; j < 112; j += nth) {
        g_bb[2 * j]     = (j < DH) ? bg[j] : 0.f;
        g_bb[2 * j + 1] = (j < DH) ? bu[j] : 0.f;
    }
    if (tid == 0) {
        g_sc[0] = 1.f / (1.f + expf(-zeta[0]));
        g_sc[1] = 1.f / (1.f + expf(-nu[0]));
    }
}

// ---------------- persistent raw-MMA recurrent kernel, 28 warps ----------------
__global__ void __launch_bounds__(NTHR)
grnn_kernel(const float* __restrict__ x, const float* __restrict__ FC,
            const float* __restrict__ FCb, float* __restrict__ out) {
    extern __shared__ __align__(16) char sm[];
    __nv_bfloat16* As = (__nv_bfloat16*)(sm + SM_A);     // double buffered
    __nv_bfloat16* Bs = (__nv_bfloat16*)(sm + SM_B);
    float2* bbs = (float2*)(sm + SM_BB);
    float*  scr = (float*)(sm + SM_SCR);

    const int tid = threadIdx.x;
    const int blk = blockIdx.x;

    // x-chunk assignment: 512 chunks; thread tid<512 owns chunk tid
    const int xr0i = tid >> 3;               // row 0..63 (valid when tid<512)
    const int xo0  = tid & 7;
    const float* xbase0 = x + (size_t)(blk * MROWS + (xr0i & 63)) * (TSTEPS * DIN) + xo0 * 4;
    const bool xact = (tid < 512);

    // ---- init: B copy, A[0] zero + x(0) split, biases ----
    {
        uint4* d = (uint4*)Bs; const uint4* s = (const uint4*)g_Bs;
        for (int i = tid; i < B_BYTES / 16; i += NTHR) d[i] = s[i];
        d = (uint4*)As;
        for (int i = tid; i < A_BYTES / 16; i += NTHR) d[i] = make_uint4(0, 0, 0, 0);
        for (int j = tid; j < 112; j += NTHR)
            bbs[j] = make_float2(g_bb[2 * j], g_bb[2 * j + 1]);
        if (xact) {
            float4 f = *(const float4*)xbase0;
            uint2 hi, lo; split4(f, hi, lo);
            char* r = (char*)As + xr0i * (A_LD * 2);
            *(uint2*)(r + 448 + xo0 * 8) = hi;
            *(uint2*)(r + 512 + xo0 * 8) = lo;
        }
    }
    __syncthreads();

    const float sz = g_sc[0];
    const float sn = g_sc[1];

    const int w    = tid >> 5;
    const int lane = tid & 31;
    const int wm   = w & 3;              // m16 tile: rows 16*wm..+15
    const int wn   = w >> 2;             // n16 tile: cols 16*wn..+15
    const int g    = lane >> 2;
    const int tg   = lane & 3;
    const int lm   = lane >> 3;
    const int lr   = lane & 7;

    uint32_t As32 = (uint32_t)__cvta_generic_to_shared(As);
    uint32_t Bs32 = (uint32_t)__cvta_generic_to_shared(Bs);
    const uint32_t aLane = (uint32_t)(((16 * wm + lr + ((lm & 1) << 3)) * A_LD + ((lm >> 1) << 3)) * 2);
    const uint32_t bAddr = Bs32 + (uint32_t)(((lr + ((lm & 1) << 3)) * B_LD + 16 * wn + ((lm >> 1) << 3)) * 2);

    // biases for this thread's cols: 16wn + 8ni + 2tg + e
    float bgv[2][2], buv[2][2];
#pragma unroll
    for (int ni = 0; ni < 2; ni++)
#pragma unroll
        for (int e = 0; e < 2; e++) {
            float2 bb = bbs[16 * wn + 8 * ni + 2 * tg + e];
            bgv[ni][e] = bb.x; buv[ni][e] = bb.y;
        }

    float H[2][4];   // [ni][c-frag], rows {g,g+8}+16wm, cols 2tg,2tg+1 +8ni+16wn
#pragma unroll
    for (int ni = 0; ni < 2; ni++)
#pragma unroll
        for (int e = 0; e < 4; e++) H[ni][e] = 0.f;

    int p = 0;
    for (int t = 0; t < TSTEPS; t++) {
        // prefetch next step's RAW x (fp32, coalesced)
        float4 xp0;
        const int hx = (t + 1 < TSTEPS);
        if (hx && xact)
            xp0 = *(const float4*)(xbase0 + (t + 1) * DIN);

        const uint32_t aAddr = As32 + p * A_BYTES + aLane;

        float c[2][4];
#pragma unroll
        for (int ni = 0; ni < 2; ni++)
#pragma unroll
            for (int e = 0; e < 4; e++) c[ni][e] = 0.f;

        // ---- 9 uniform units ----
#pragma unroll
        for (int u = 0; u < 9; u++) {
            uint32_t ka = aAddr + OFF_AH(u);
            uint32_t a0, a1, a2, a3, l0, l1, l2, l3;
            LDSM4(a0, a1, a2, a3, ka);
            LDSM4(l0, l1, l2, l3, ka + OFF_ALD(u));
            uint32_t kb = bAddr + OFF_BH(u);
            uint32_t b0, b1, b2, b3, q0, q1, q2, q3;
            LDSM4T(b0, b1, b2, b3, kb);
            LDSM4T(q0, q1, q2, q3, kb + OFF_BLD(u));
            MMA(c[0][0], c[0][1], c[0][2], c[0][3], a0, a1, a2, a3, b0, b1);
            MMA(c[1][0], c[1][1], c[1][2], c[1][3], a0, a1, a2, a3, b2, b3);
            MMA(c[0][0], c[0][1], c[0][2], c[0][3], l0, l1, l2, l3, b0, b1);
            MMA(c[1][0], c[1][1], c[1][2], c[1][3], l0, l1, l2, l3, b2, b3);
            MMA(c[0][0], c[0][1], c[0][2], c[0][3], a0, a1, a2, a3, q0, q1);
            MMA(c[1][0], c[1][1], c[1][2], c[1][3], a0, a1, a2, a3, q2, q3);
        }

        // ---- in-register gate epilogue ----
#pragma unroll
        for (int ni = 0; ni < 2; ni++) {
            int col0 = 16 * wn + 8 * ni + 2 * tg;
#pragma unroll
            for (int e = 0; e < 4; e++) {
                int ee = e & 1;
                float cc = c[ni][e];
                float gg = fmaf(0.5f, tanha(0.5f * (cc + bgv[ni][ee])), 0.5f);
                float hh = tanha(cc + buv[ni][ee]);
                float hn = fmaf(gg, H[ni][e] - sz, fmaf(sn, hh, sz));
                H[ni][e] = (col0 + ee < DH) ? hn : 0.f;
            }
        }

        // ---- write H + split x into the OTHER buffer ----
        char* Aw = (char*)As + (p ^ 1) * A_BYTES;
        {
            int r0 = 16 * wm + g;
#pragma unroll
            for (int ni = 0; ni < 2; ni++) {
                int col0 = 16 * wn + 8 * ni + 2 * tg;
                uint32_t lo0, lo1;
                uint32_t hi0 = bfsplit(H[ni][0], H[ni][1], lo0);
                uint32_t hi1 = bfsplit(H[ni][2], H[ni][3], lo1);
                char* p0 = Aw + (r0 * A_LD + col0) * 2;
                char* p1 = Aw + ((r0 + 8) * A_LD + col0) * 2;
                *(uint32_t*)p0 = hi0;  *(uint32_t*)(p0 + 224) = lo0;
                *(uint32_t*)p1 = hi1;  *(uint32_t*)(p1 + 224) = lo1;
            }
        }
        if (hx && xact) {
            uint2 hi, lo; split4(xp0, hi, lo);
            char* r = Aw + xr0i * (A_LD * 2);
            *(uint2*)(r + 448 + xo0 * 8) = hi;
            *(uint2*)(r + 512 + xo0 * 8) = lo;
        }
        __syncthreads();
        p ^= 1;
    }

    // ---- scores ----
    for (int i = tid; i < MROWS * NCLS; i += NTHR) scr[i] = 0.f;
    __syncthreads();
#pragma unroll
    for (int half = 0; half < 2; half++) {
        int row = 16 * wm + g + 8 * half;
        float s[NCLS];
#pragma unroll
        for (int cix = 0; cix < NCLS; cix++) s[cix] = 0.f;
#pragma unroll
        for (int ni = 0; ni < 2; ni++)
#pragma unroll
            for (int e = 0; e < 2; e++) {
                int col = 16 * wn + 8 * ni + 2 * tg + e;
                if (col < DH) {
                    float hv = H[ni][2 * half + e];
#pragma unroll
                    for (int cix = 0; cix < NCLS; cix++)
                        s[cix] = fmaf(hv, __ldg(FC + col * NCLS + cix), s[cix]);
                }
            }
#pragma unroll
        for (int cix = 0; cix < NCLS; cix++)
            atomicAdd(&scr[row * NCLS + cix], s[cix]);
    }
    __syncthreads();
    if (tid < MROWS) {
        int grow = blk * MROWS + tid;
#pragma unroll
        for (int cix = 0; cix < NCLS; cix++)
            out[(size_t)grow * NCLS + cix] = scr[tid * NCLS + cix] + __ldg(FCb + cix);
    }
}

// ---------------- launch ----------------
extern "C" void kernel_launch(void* const* d_in, const int* in_sizes, int n_in,
                              void* d_out, int out_size) {
    const float* x    = (const float*)d_in[0];
    const float* W1   = (const float*)d_in[1];
    const float* W2   = (const float*)d_in[2];
    const float* U1   = (const float*)d_in[3];
    const float* U2   = (const float*)d_in[4];
    const float* bg   = (const float*)d_in[5];
    const float* bu   = (const float*)d_in[6];
    const float* zeta = (const float*)d_in[7];
    const float* nu   = (const float*)d_in[8];
    const float* FC   = (const float*)d_in[9];
    const float* FCb  = (const float*)d_in[10];
    float* out = (float*)d_out;

    cudaFuncSetAttribute(grnn_kernel, cudaFuncAttributeMaxDynamicSharedMemorySize, SM_TOT);

    setup_w<<<16, 256>>>(W1, W2, U1, U2, bg, bu, zeta, nu);
    grnn_kernel<<<NBLK, NTHR, SM_TOT>>>(x, FC, FCb, out);
}

// round 17
// speedup vs baseline: 1.5546x; 1.1719x over previous
#include <cuda_runtime.h>
#include <cuda_bf16.h>
#include <math.h>
#include <stdint.h>

// ---------------- problem constants ----------------
#define BATCH   8192
#define TSTEPS  99
#define DIN     32
#define DH      100
#define RW      16
#define RU      25
#define NCLS    6
#define MROWS   64
#define NBLK    (BATCH / MROWS)      // 128
#define NTHR    896                  // 28 warps: 4(m) x 7(n)

// A: 64 x 296 bf16. cols: 0-111 Hhi, 112-223 Hlo, 224-255 xhi, 256-287 xlo
#define A_LD    296
#define A_BYTES (64 * A_LD * 2)      // 37888
// B: 288 x 136 bf16. rows: 0-111 Uhi, 112-223 Ulo, 224-255 Whi, 256-287 Wlo
#define B_LD    136
#define B_BYTES (288 * B_LD * 2)     // 78336

#define SM_A    0                    // double buffered: A[0], A[1]
#define SM_B    (SM_A + 2 * A_BYTES)
#define SM_BB   (SM_B + B_BYTES)
#define SM_SCR  (SM_BB + 1024)
#define SM_TOT  (SM_SCR + 1536)      // 156672 B

// ---------------- device-global prepped data ----------------
__device__ __align__(16) __nv_bfloat16 g_Bs[288 * B_LD];
__device__ float g_bb[224];
__device__ float g_sc[2];

__device__ __forceinline__ float tanha(float v) {
    float r; asm("tanh.approx.f32 %0, %1;" : "=f"(r) : "f"(v)); return r;
}
__device__ __forceinline__ uint32_t pk2(__nv_bfloat16 a, __nv_bfloat16 b) {
    return (uint32_t)__bfloat16_as_ushort(a) | ((uint32_t)__bfloat16_as_ushort(b) << 16);
}
__device__ __forceinline__ uint32_t bfsplit(float v0, float v1, uint32_t& lo) {
    __nv_bfloat16 h0 = __float2bfloat16_rn(v0);
    __nv_bfloat16 h1 = __float2bfloat16_rn(v1);
    lo = pk2(__float2bfloat16_rn(v0 - __bfloat162float(h0)),
             __float2bfloat16_rn(v1 - __bfloat162float(h1)));
    return pk2(h0, h1);
}
__device__ __forceinline__ void split4(float4 f, uint2& hi, uint2& lo) {
    uint32_t l01, l23;
    uint32_t h01 = bfsplit(f.x, f.y, l01);
    uint32_t h23 = bfsplit(f.z, f.w, l23);
    hi = make_uint2(h01, h23);
    lo = make_uint2(l01, l23);
}

#define LDSM4(r0,r1,r2,r3,a) \
    asm volatile("ldmatrix.sync.aligned.m8n8.x4.shared.b16 {%0,%1,%2,%3}, [%4];" \
                 : "=r"(r0),"=r"(r1),"=r"(r2),"=r"(r3) : "r"(a))
#define LDSM4T(r0,r1,r2,r3,a) \
    asm volatile("ldmatrix.sync.aligned.m8n8.x4.trans.shared.b16 {%0,%1,%2,%3}, [%4];" \
                 : "=r"(r0),"=r"(r1),"=r"(r2),"=r"(r3) : "r"(a))
#define MMA(c0,c1,c2,c3,a0,a1,a2,a3,b0,b1) \
    asm volatile("mma.sync.aligned.m16n8k16.row.col.f32.bf16.bf16.f32 " \
                 "{%0,%1,%2,%3}, {%4,%5,%6,%7}, {%8,%9}, {%0,%1,%2,%3};" \
                 : "+f"(c0),"+f"(c1),"+f"(c2),"+f"(c3) \
                 : "r"(a0),"r"(a1),"r"(a2),"r"(a3),"r"(b0),"r"(b1))
#define GROUP_BAR(id) \
    asm volatile("bar.sync %0, %1;" :: "r"(id), "r"(224) : "memory")

// per-unit byte offsets (u = 0..6 H k-units, u = 7..8 x k-units)
#define OFF_AH(u)  ((u) < 7 ? (u) * 32 : 448 + 32 * ((u) - 7))
#define OFF_ALD(u) ((u) < 7 ? 224 : 64)
#define OFF_BH(u)  ((u) < 7 ? (u) * 16 * B_LD * 2 : (224 + 16 * ((u) - 7)) * B_LD * 2)
#define OFF_BLD(u) ((u) < 7 ? 112 * B_LD * 2 : 32 * B_LD * 2)

// ---------------- setup: weights -> split B image (verbatim) ----------------
__global__ void setup_w(const float* __restrict__ W1, const float* __restrict__ W2,
                        const float* __restrict__ U1, const float* __restrict__ U2,
                        const float* __restrict__ bg, const float* __restrict__ bu,
                        const float* __restrict__ zeta, const float* __restrict__ nu) {
    int tid = blockIdx.x * blockDim.x + threadIdx.x;
    int nth = gridDim.x * blockDim.x;
    for (int idx = tid; idx < 288 * B_LD; idx += nth) {
        int k = idx / B_LD, n = idx % B_LD;
        float v = 0.f;
        bool lo = false;
        if (n < DH) {
            if (k < 112) {
                if (k < DH)
                    for (int r = 0; r < RU; r++) v = fmaf(U1[k * RU + r], U2[r * DH + n], v);
            } else if (k < 224) {
                int kk = k - 112; lo = true;
                if (kk < DH)
                    for (int r = 0; r < RU; r++) v = fmaf(U1[kk * RU + r], U2[r * DH + n], v);
            } else if (k < 256) {
                int kk = k - 224;
                for (int r = 0; r < RW; r++) v = fmaf(W1[kk * RW + r], W2[r * DH + n], v);
            } else {
                int kk = k - 256; lo = true;
                for (int r = 0; r < RW; r++) v = fmaf(W1[kk * RW + r], W2[r * DH + n], v);
            }
        }
        __nv_bfloat16 hi = __float2bfloat16_rn(v);
        g_Bs[idx] = lo ? __float2bfloat16_rn(v - __bfloat162float(hi)) : hi;
    }
    for (int j = tid; j < 112; j += nth) {
        g_bb[2 * j]     = (j < DH) ? bg[j] : 0.f;
        g_bb[2 * j + 1] = (j < DH) ? bu[j] : 0.f;
    }
    if (tid == 0) {
        g_sc[0] = 1.f / (1.f + expf(-zeta[0]));
        g_sc[1] = 1.f / (1.f + expf(-nu[0]));
    }
}

// ---------------- persistent raw-MMA recurrent kernel, 4 indep groups ----------------
__global__ void __launch_bounds__(NTHR)
grnn_kernel(const float* __restrict__ x, const float* __restrict__ FC,
            const float* __restrict__ FCb, float* __restrict__ out) {
    extern __shared__ __align__(16) char sm[];
    __nv_bfloat16* As = (__nv_bfloat16*)(sm + SM_A);     // double buffered
    __nv_bfloat16* Bs = (__nv_bfloat16*)(sm + SM_B);
    float2* bbs = (float2*)(sm + SM_BB);
    float*  scr = (float*)(sm + SM_SCR);

    const int tid = threadIdx.x;
    const int blk = blockIdx.x;

    const int w    = tid >> 5;
    const int lane = tid & 31;
    const int wm   = w & 3;              // m16 tile / barrier group
    const int wn   = w >> 2;             // n16 tile (0..6)
    const int g    = lane >> 2;
    const int tg   = lane & 3;
    const int lm   = lane >> 3;
    const int lr   = lane & 7;

    // group-local x staging: li = wn*32+lane (0..223); li<128 stages
    // row 16*wm + (li>>3), 4 floats at chunk (li&7)
    const int li   = wn * 32 + lane;
    const bool xact = (li < 128);
    const int xrow = 16 * wm + (li >> 3);     // local row
    const int xo0  = li & 7;
    const float* xbase0 = x + (size_t)(blk * MROWS + xrow) * (TSTEPS * DIN) + xo0 * 4;

    // ---- init: B copy, A[0] zero + x(0) split, biases ----
    {
        uint4* d = (uint4*)Bs; const uint4* s = (const uint4*)g_Bs;
        for (int i = tid; i < B_BYTES / 16; i += NTHR) d[i] = s[i];
        d = (uint4*)As;
        for (int i = tid; i < A_BYTES / 16; i += NTHR) d[i] = make_uint4(0, 0, 0, 0);
        for (int j = tid; j < 112; j += NTHR)
            bbs[j] = make_float2(g_bb[2 * j], g_bb[2 * j + 1]);
    }
    __syncthreads();
    if (xact) {
        float4 f = *(const float4*)xbase0;
        uint2 hi, lo; split4(f, hi, lo);
        char* r = (char*)As + xrow * (A_LD * 2);
        *(uint2*)(r + 448 + xo0 * 8) = hi;
        *(uint2*)(r + 512 + xo0 * 8) = lo;
    }
    __syncthreads();

    const float sz = g_sc[0];
    const float sn = g_sc[1];

    uint32_t As32 = (uint32_t)__cvta_generic_to_shared(As);
    uint32_t Bs32 = (uint32_t)__cvta_generic_to_shared(Bs);
    const uint32_t aLane = (uint32_t)(((16 * wm + lr + ((lm & 1) << 3)) * A_LD + ((lm >> 1) << 3)) * 2);
    const uint32_t bAddr = Bs32 + (uint32_t)(((lr + ((lm & 1) << 3)) * B_LD + 16 * wn + ((lm >> 1) << 3)) * 2);

    // biases for this thread's cols
    float bgv[2][2], buv[2][2];
#pragma unroll
    for (int ni = 0; ni < 2; ni++)
#pragma unroll
        for (int e = 0; e < 2; e++) {
            float2 bb = bbs[16 * wn + 8 * ni + 2 * tg + e];
            bgv[ni][e] = bb.x; buv[ni][e] = bb.y;
        }

    float H[2][4];
#pragma unroll
    for (int ni = 0; ni < 2; ni++)
#pragma unroll
        for (int e = 0; e < 4; e++) H[ni][e] = 0.f;

    const int barid = wm + 1;

    int p = 0;
    for (int t = 0; t < TSTEPS; t++) {
        // prefetch next step's RAW x (fp32, coalesced)
        float4 xp0;
        const int hx = (t + 1 < TSTEPS);
        if (hx && xact)
            xp0 = *(const float4*)(xbase0 + (t + 1) * DIN);

        const uint32_t aAddr = As32 + p * A_BYTES + aLane;

        float c[2][4];
#pragma unroll
        for (int ni = 0; ni < 2; ni++)
#pragma unroll
            for (int e = 0; e < 4; e++) c[ni][e] = 0.f;

        // ---- 9 uniform units ----
#pragma unroll
        for (int u = 0; u < 9; u++) {
            uint32_t ka = aAddr + OFF_AH(u);
            uint32_t a0, a1, a2, a3, l0, l1, l2, l3;
            LDSM4(a0, a1, a2, a3, ka);
            LDSM4(l0, l1, l2, l3, ka + OFF_ALD(u));
            uint32_t kb = bAddr + OFF_BH(u);
            uint32_t b0, b1, b2, b3, q0, q1, q2, q3;
            LDSM4T(b0, b1, b2, b3, kb);
            LDSM4T(q0, q1, q2, q3, kb + OFF_BLD(u));
            MMA(c[0][0], c[0][1], c[0][2], c[0][3], a0, a1, a2, a3, b0, b1);
            MMA(c[1][0], c[1][1], c[1][2], c[1][3], a0, a1, a2, a3, b2, b3);
            MMA(c[0][0], c[0][1], c[0][2], c[0][3], l0, l1, l2, l3, b0, b1);
            MMA(c[1][0], c[1][1], c[1][2], c[1][3], l0, l1, l2, l3, b2, b3);
            MMA(c[0][0], c[0][1], c[0][2], c[0][3], a0, a1, a2, a3, q0, q1);
            MMA(c[1][0], c[1][1], c[1][2], c[1][3], a0, a1, a2, a3, q2, q3);
        }

        // ---- in-register gate epilogue ----
#pragma unroll
        for (int ni = 0; ni < 2; ni++) {
            int col0 = 16 * wn + 8 * ni + 2 * tg;
#pragma unroll
            for (int e = 0; e < 4; e++) {
                int ee = e & 1;
                float cc = c[ni][e];
                float gg = fmaf(0.5f, tanha(0.5f * (cc + bgv[ni][ee])), 0.5f);
                float hh = tanha(cc + buv[ni][ee]);
                float hn = fmaf(gg, H[ni][e] - sz, fmaf(sn, hh, sz));
                H[ni][e] = (col0 + ee < DH) ? hn : 0.f;
            }
        }

        // ---- write H + split x into the OTHER buffer (group-local rows) ----
        char* Aw = (char*)As + (p ^ 1) * A_BYTES;
        {
            int r0 = 16 * wm + g;
#pragma unroll
            for (int ni = 0; ni < 2; ni++) {
                int col0 = 16 * wn + 8 * ni + 2 * tg;
                uint32_t lo0, lo1;
                uint32_t hi0 = bfsplit(H[ni][0], H[ni][1], lo0);
                uint32_t hi1 = bfsplit(H[ni][2], H[ni][3], lo1);
                char* p0 = Aw + (r0 * A_LD + col0) * 2;
                char* p1 = Aw + ((r0 + 8) * A_LD + col0) * 2;
                *(uint32_t*)p0 = hi0;  *(uint32_t*)(p0 + 224) = lo0;
                *(uint32_t*)p1 = hi1;  *(uint32_t*)(p1 + 224) = lo1;
            }
        }
        if (hx && xact) {
            uint2 hi, lo; split4(xp0, hi, lo);
            char* r = Aw + xrow * (A_LD * 2);
            *(uint2*)(r + 448 + xo0 * 8) = hi;
            *(uint2*)(r + 512 + xo0 * 8) = lo;
        }
        GROUP_BAR(barid);      // only the 7 warps sharing this m-block
        p ^= 1;
    }

    // ---- scores (full-CTA convergence first) ----
    __syncthreads();
    for (int i = tid; i < MROWS * NCLS; i += NTHR) scr[i] = 0.f;
    __syncthreads();
#pragma unroll
    for (int half = 0; half < 2; half++) {
        int row = 16 * wm + g + 8 * half;
        float s[NCLS];
#pragma unroll
        for (int cix = 0; cix < NCLS; cix++) s[cix] = 0.f;
#pragma unroll
        for (int ni = 0; ni < 2; ni++)
#pragma unroll
            for (int e = 0; e < 2; e++) {
                int col = 16 * wn + 8 * ni + 2 * tg + e;
                if (col < DH) {
                    float hv = H[ni][2 * half + e];
#pragma unroll
                    for (int cix = 0; cix < NCLS; cix++)
                        s[cix] = fmaf(hv, __ldg(FC + col * NCLS + cix), s[cix]);
                }
            }
#pragma unroll
        for (int cix = 0; cix < NCLS; cix++)
            atomicAdd(&scr[row * NCLS + cix], s[cix]);
    }
    __syncthreads();
    if (tid < MROWS) {
        int grow = blk * MROWS + tid;
#pragma unroll
        for (int cix = 0; cix < NCLS; cix++)
            out[(size_t)grow * NCLS + cix] = scr[tid * NCLS + cix] + __ldg(FCb + cix);
    }
}

// ---------------- launch ----------------
extern "C" void kernel_launch(void* const* d_in, const int* in_sizes, int n_in,
                              void* d_out, int out_size) {
    const float* x    = (const float*)d_in[0];
    const float* W1   = (const float*)d_in[1];
    const float* W2   = (const float*)d_in[2];
    const float* U1   = (const float*)d_in[3];
    const float* U2   = (const float*)d_in[4];
    const float* bg   = (const float*)d_in[5];
    const float* bu   = (const float*)d_in[6];
    const float* zeta = (const float*)d_in[7];
    const float* nu   = (const float*)d_in[8];
    const float* FC   = (const float*)d_in[9];
    const float* FCb  = (const float*)d_in[10];
    float* out = (float*)d_out;

    cudaFuncSetAttribute(grnn_kernel, cudaFuncAttributeMaxDynamicSharedMemorySize, SM_TOT);

    setup_w<<<16, 256>>>(W1, W2, U1, U2, bg, bu, zeta, nu);
    grnn_kernel<<<NBLK, NTHR, SM_TOT>>>(x, FC, FCb, out);
}